// round 1
// baseline (speedup 1.0000x reference)
#include <cuda_runtime.h>
#include <math.h>

#define NQ    20
#define NL    4
#define BATCH 16
#define DIM   (1 << NQ)
#define TOTAL (BATCH * DIM)

// Scratch ping-pong buffers (allocation-free: __device__ globals)
__device__ float  g_bufA[TOTAL];
__device__ float  g_bufB[TOTAL];
__device__ float2 g_cs[NL * NQ];   // (cos(theta/2), sin(theta/2)) per gate

// ---------------------------------------------------------------------------
// Precompute rotation coefficients (theta lives on device)
// ---------------------------------------------------------------------------
__global__ void sincos_kernel(const float* __restrict__ theta) {
    int i = threadIdx.x;
    if (i < NL * NQ) {
        float t = 0.5f * theta[i];
        g_cs[i] = make_float2(cosf(t), sinf(t));
    }
}

// ---------------------------------------------------------------------------
// Butterfly helpers. RY: a' = c*a - s*b ; b' = s*a + c*b
// ---------------------------------------------------------------------------
__device__ __forceinline__ void stage_xlane(float e[32], int kbit, float c, float s, int lane) {
    float ss = ((lane >> kbit) & 1) ? s : -s;
#pragma unroll
    for (int j = 0; j < 32; j++) {
        float o = __shfl_xor_sync(0xffffffffu, e[j], 1 << kbit);
        e[j] = fmaf(c, e[j], ss * o);
    }
}

__device__ __forceinline__ void stage_reg(float e[32], int m, float c, float s) {
#pragma unroll
    for (int j = 0; j < 32; j++) {
        if ((j & m) == 0) {
            float a = e[j], b = e[j | m];
            e[j]     = fmaf(c, a, -s * b);
            e[j | m] = fmaf(s, a,  c * b);
        }
    }
}

// ---------------------------------------------------------------------------
// HIGH kernel: qubits 0..9 (index strides 2^19..2^10).
// Each block: 8 "columns" (fixed low-10-bits values), 1024 h-values each.
// Coalesced load -> smem -> each warp owns one column in registers
// (h = j*32 + t), 5 shuffle stages + 5 register stages -> smem -> coalesced store.
// GRAY: fold the previous layer's CNOT-chain permutation into the gather.
// ---------------------------------------------------------------------------
template <bool GRAY>
__global__ void __launch_bounds__(256) high_kernel(const float* __restrict__ in,
                                                   float* __restrict__ out,
                                                   int layer) {
    __shared__ float sm[1024 * 9];     // 8 cols, padded row of 9 -> conflict-free
    const int tid = threadIdx.x;
    const int blk = blockIdx.x;        // 2048 blocks = 16 batches * 128 lowgroups
    const int b   = blk >> 7;
    const int lg  = blk & 127;
    const int lowbase = lg * 8;
    const size_t base = (size_t)b << NQ;

#pragma unroll
    for (int r = 0; r < 32; r++) {
        int idx = r * 256 + tid;
        int h = idx >> 3, c = idx & 7;
        int gi  = (h << 10) + lowbase + c;
        int src = GRAY ? (gi ^ (gi >> 1)) : gi;
        sm[h * 9 + c] = in[base + src];
    }
    __syncthreads();

    const int w = tid >> 5, t = tid & 31;
    float e[32];
#pragma unroll
    for (int j = 0; j < 32; j++) e[j] = sm[(j * 32 + t) * 9 + w];

    const float2* cs = g_cs + layer * NQ;
    // h bit k  <->  qubit (9-k)
#pragma unroll
    for (int k = 0; k < 5; k++) { float2 v = cs[9 - k]; stage_xlane(e, k, v.x, v.y, t); }
#pragma unroll
    for (int k = 5; k < 10; k++) { float2 v = cs[9 - k]; stage_reg(e, 1 << (k - 5), v.x, v.y); }

#pragma unroll
    for (int j = 0; j < 32; j++) sm[(j * 32 + t) * 9 + w] = e[j];
    __syncthreads();

#pragma unroll
    for (int r = 0; r < 32; r++) {
        int idx = r * 256 + tid;
        int h = idx >> 3, c = idx & 7;
        out[base + (h << 10) + lowbase + c] = sm[h * 9 + c];
    }
}

// ---------------------------------------------------------------------------
// LOW kernel: qubits 10..19 (strides 512..1) inside contiguous 1024-float
// tiles. One warp per tile, 32 regs/thread, float4 I/O, no shared memory.
// Element r = j4*4+k holds index j4*128 + t*4 + k within the tile:
//   in-thread masks: m=1 (bit0,q19)  m=2 (bit1,q18)  m=4 (bit7,q12)
//                    m=8 (bit8,q11)  m=16 (bit9,q10)
//   cross-lane:      lane bit k -> index bit 2+k -> qubit 17-k
// FINAL: fold the last CNOT-chain permutation + abs into the store:
//   out[grayDecode(g)] = |v|  (scatter stays within one 128B line per warp).
// ---------------------------------------------------------------------------
template <bool FINAL>
__global__ void __launch_bounds__(256) low_kernel(const float* __restrict__ in,
                                                  float* __restrict__ out,
                                                  int layer) {
    const int tid = threadIdx.x;
    const int w = tid >> 5, t = tid & 31;
    const size_t tile = ((size_t)blockIdx.x * 8 + w) << 10;

    float e[32];
    const float4* in4 = (const float4*)(in + tile);
#pragma unroll
    for (int j4 = 0; j4 < 8; j4++) {
        float4 v = in4[j4 * 32 + t];
        e[j4 * 4 + 0] = v.x; e[j4 * 4 + 1] = v.y;
        e[j4 * 4 + 2] = v.z; e[j4 * 4 + 3] = v.w;
    }

    const float2* cs = g_cs + layer * NQ;
    { float2 v = cs[19]; stage_reg(e, 1, v.x, v.y); }
    { float2 v = cs[18]; stage_reg(e, 2, v.x, v.y); }
#pragma unroll
    for (int k = 0; k < 5; k++) { float2 v = cs[17 - k]; stage_xlane(e, k, v.x, v.y, t); }
    { float2 v = cs[12]; stage_reg(e,  4, v.x, v.y); }
    { float2 v = cs[11]; stage_reg(e,  8, v.x, v.y); }
    { float2 v = cs[10]; stage_reg(e, 16, v.x, v.y); }

    if (!FINAL) {
        float4* out4 = (float4*)(out + tile);
#pragma unroll
        for (int j4 = 0; j4 < 8; j4++) {
            out4[j4 * 32 + t] = make_float4(e[j4 * 4 + 0], e[j4 * 4 + 1],
                                            e[j4 * 4 + 2], e[j4 * 4 + 3]);
        }
    } else {
        const size_t bbase = tile & ~((size_t)(DIM - 1));
        const int    ibase = (int)(tile & (DIM - 1));
#pragma unroll
        for (int r = 0; r < 32; r++) {
            int j4 = r >> 2, k = r & 3;
            int gi = ibase + j4 * 128 + t * 4 + k;
            int p = gi;                     // gray-decode: p s.t. p^(p>>1) = gi
            p ^= p >> 1; p ^= p >> 2; p ^= p >> 4; p ^= p >> 8; p ^= p >> 16;
            out[bbase + p] = fabsf(e[r]);
        }
    }
}

// ---------------------------------------------------------------------------
extern "C" void kernel_launch(void* const* d_in, const int* in_sizes, int n_in,
                              void* d_out, int out_size) {
    const float* x     = (const float*)d_in[0];
    const float* theta = (const float*)d_in[1];
    float*       out   = (float*)d_out;

    float *bA = nullptr, *bB = nullptr;
    cudaGetSymbolAddress((void**)&bA, g_bufA);
    cudaGetSymbolAddress((void**)&bB, g_bufB);

    sincos_kernel<<<1, 128>>>(theta);

    // Layer 0: input x, no pending permutation
    high_kernel<false><<<2048, 256>>>(x,  bA, 0);
    low_kernel<false><<<2048, 256>>>(bA, bB, 0);
    // Layers 1..2: gather with gray (pending CNOT-chain perm), linear out
    high_kernel<true><<<2048, 256>>>(bB, bA, 1);
    low_kernel<false><<<2048, 256>>>(bA, bB, 1);
    high_kernel<true><<<2048, 256>>>(bB, bA, 2);
    low_kernel<false><<<2048, 256>>>(bA, bB, 2);
    // Layer 3: final LOW folds last perm + abs into the output scatter
    high_kernel<true><<<2048, 256>>>(bB, bA, 3);
    low_kernel<true><<<2048, 256>>>(bA, out, 3);
}

// round 2
// speedup vs baseline: 1.2714x; 1.2714x over previous
#include <cuda_runtime.h>
#include <math.h>

#define NQ    20
#define NL    4
#define BATCH 16
#define DIM   (1 << NQ)
#define TOTAL (BATCH * DIM)

// Scratch ping-pong buffers (allocation-free: __device__ globals)
__device__ float  g_bufA[TOTAL];
__device__ float  g_bufB[TOTAL];
__device__ float2 g_cs[NL * NQ];   // (cos(theta/2), sin(theta/2)) per gate

// ---------------------------------------------------------------------------
__global__ void sincos_kernel(const float* __restrict__ theta) {
    int i = threadIdx.x;
    if (i < NL * NQ) {
        float t = 0.5f * theta[i];
        g_cs[i] = make_float2(cosf(t), sinf(t));
    }
}

// RY butterfly: a' = c*a - s*b ; b' = s*a + c*b
__device__ __forceinline__ void stage_xlane(float e[32], int kbit, float2 v, int lane) {
    float ss = ((lane >> kbit) & 1) ? v.y : -v.y;
#pragma unroll
    for (int j = 0; j < 32; j++) {
        float o = __shfl_xor_sync(0xffffffffu, e[j], 1 << kbit);
        e[j] = fmaf(v.x, e[j], ss * o);
    }
}

__device__ __forceinline__ void stage_reg(float e[32], int m, float2 v) {
#pragma unroll
    for (int j = 0; j < 32; j++) {
        if ((j & m) == 0) {
            float a = e[j], b = e[j | m];
            e[j]     = fmaf(v.x, a, -v.y * b);
            e[j | m] = fmaf(v.y, a,  v.x * b);
        }
    }
}

// gray decode (p such that p ^ (p>>1) = g)
__device__ __host__ __forceinline__ constexpr int gdec(int g) {
    int p = g;
    p ^= p >> 1; p ^= p >> 2; p ^= p >> 4; p ^= p >> 8; p ^= p >> 16;
    return p;
}

// ---------------------------------------------------------------------------
// HIGH kernel: qubits 0..4 (index bits 19:15, k stride 2^15).
// Thread owns ONE low-position and all 32 k values -> pure register
// butterflies, no smem, no shuffles, fully coalesced, in-place capable.
// index = (batch<<20) + k*32768 + pos ;  k bit b <-> qubit 4-b
// ---------------------------------------------------------------------------
__global__ void __launch_bounds__(512, 3) high_kernel(const float* __restrict__ in,
                                                      float* __restrict__ out,
                                                      int layer) {
    // grid = 1024: 16 batches * 64 windows of 512 positions
    const int blk = blockIdx.x;
    const size_t off = ((size_t)(blk >> 6) << 20) + (size_t)(blk & 63) * 512 + threadIdx.x;

    float e[32];
    const float* p = in + off;
#pragma unroll
    for (int k = 0; k < 32; k++) e[k] = p[(size_t)k << 15];

    const float2* cs = g_cs + layer * NQ;
    stage_reg(e, 1,  cs[4]);
    stage_reg(e, 2,  cs[3]);
    stage_reg(e, 4,  cs[2]);
    stage_reg(e, 8,  cs[1]);
    stage_reg(e, 16, cs[0]);

    float* q = out + off;
#pragma unroll
    for (int k = 0; k < 32; k++) q[(size_t)k << 15] = e[k];
}

// ---------------------------------------------------------------------------
// LOW kernel: qubits 5..19 inside contiguous 32768-float tiles.
// 1024 threads, 32 regs/thread. m = local 15-bit index; m bit b <-> qubit 19-b.
// Phase1 (m = j*1024 + w*32 + t): shuffle bits 4:0 (q19..15), reg bits 14:10 (q9..5)
// Transpose (conflict-free: lane bits unchanged, rows contiguous)
// Phase2 (m = w*1024 + j*32 + t): reg bits 9:5 (q14..10)
// Store folds the CNOT-chain permutation: out[gdec(g)] = v (and fabs if FINAL).
// ---------------------------------------------------------------------------
template <bool FINAL>
__global__ void __launch_bounds__(1024, 1) low_kernel(const float* __restrict__ in,
                                                      float* __restrict__ out,
                                                      int layer) {
    extern __shared__ float sm[];          // 32768 floats = 128 KB
    const int t = threadIdx.x & 31;
    const int w = threadIdx.x >> 5;
    const size_t tbase = (size_t)blockIdx.x << 15;   // grid = 512 tiles

    float e[32];
    const float* p = in + tbase;
#pragma unroll
    for (int j = 0; j < 32; j++) e[j] = p[j * 1024 + w * 32 + t];

    const float2* cs = g_cs + layer * NQ;
    // shuffle stages: lane bit k <-> qubit 19-k
    stage_xlane(e, 0, cs[19], t);
    stage_xlane(e, 1, cs[18], t);
    stage_xlane(e, 2, cs[17], t);
    stage_xlane(e, 3, cs[16], t);
    stage_xlane(e, 4, cs[15], t);
    // reg stages: j bit b <-> m bit 10+b <-> qubit 9-b
    stage_reg(e, 1,  cs[9]);
    stage_reg(e, 2,  cs[8]);
    stage_reg(e, 4,  cs[7]);
    stage_reg(e, 8,  cs[6]);
    stage_reg(e, 16, cs[5]);

    // transpose: swap reg-index bits (14:10) with warp-index bits (9:5)
#pragma unroll
    for (int j = 0; j < 32; j++) sm[j * 1024 + w * 32 + t] = e[j];
    __syncthreads();
#pragma unroll
    for (int j = 0; j < 32; j++) e[j] = sm[w * 1024 + j * 32 + t];

    // reg stages: j bit b <-> m bit 5+b <-> qubit 14-b
    stage_reg(e, 1,  cs[14]);
    stage_reg(e, 2,  cs[13]);
    stage_reg(e, 4,  cs[12]);
    stage_reg(e, 8,  cs[11]);
    stage_reg(e, 16, cs[10]);

    // store with gray-decode permutation (linear over disjoint bit fields)
    const int    tile20 = (int)(tbase & (DIM - 1));          // bits 19:15
    const size_t bbase  = tbase & ~((size_t)(DIM - 1));      // batch base
    const int    pbase  = gdec(tile20 + (w << 10) + t);
#pragma unroll
    for (int j = 0; j < 32; j++) {
        int pp = pbase ^ gdec(j << 5);     // gdec(j<<5) folds to a constant
        if (FINAL) out[bbase + pp] = fabsf(e[j]);
        else       out[bbase + pp] = e[j];
    }
}

// ---------------------------------------------------------------------------
extern "C" void kernel_launch(void* const* d_in, const int* in_sizes, int n_in,
                              void* d_out, int out_size) {
    const float* x     = (const float*)d_in[0];
    const float* theta = (const float*)d_in[1];
    float*       out   = (float*)d_out;

    float *bA = nullptr, *bB = nullptr;
    cudaGetSymbolAddress((void**)&bA, g_bufA);
    cudaGetSymbolAddress((void**)&bB, g_bufB);

    const int SMEM = 32768 * sizeof(float);
    cudaFuncSetAttribute(low_kernel<false>, cudaFuncAttributeMaxDynamicSharedMemorySize, SMEM);
    cudaFuncSetAttribute(low_kernel<true>,  cudaFuncAttributeMaxDynamicSharedMemorySize, SMEM);

    sincos_kernel<<<1, 128>>>(theta);

    // layer 0
    high_kernel<<<1024, 512>>>(x,  bA, 0);       // out-of-place (x is read-only)
    low_kernel<false><<<512, 1024, SMEM>>>(bA, bB, 0);
    // layer 1
    high_kernel<<<1024, 512>>>(bB, bB, 1);       // in-place (no permutation)
    low_kernel<false><<<512, 1024, SMEM>>>(bB, bA, 1);
    // layer 2
    high_kernel<<<1024, 512>>>(bA, bA, 2);
    low_kernel<false><<<512, 1024, SMEM>>>(bA, bB, 2);
    // layer 3
    high_kernel<<<1024, 512>>>(bB, bB, 3);
    low_kernel<true><<<512, 1024, SMEM>>>(bB, out, 3);
}

// round 3
// speedup vs baseline: 1.3317x; 1.0475x over previous
#include <cuda_runtime.h>
#include <math.h>
#include <stdint.h>

#define NQ    20
#define NL    4
#define BATCH 16
#define DIM   (1 << NQ)
#define TOTAL (BATCH * DIM)

// Scratch ping-pong buffers (allocation-free: __device__ globals)
__device__ float  g_bufA[TOTAL];
__device__ float  g_bufB[TOTAL];
__device__ float2 g_rf[NL * NQ];   // .x = ratio (|r|<=1), .y = form (0 or 1)
__device__ float  g_absC;          // |product of per-gate scales|

// ---------------------------------------------------------------------------
// Precompute fast-Givens data.
//   form0 (|c|>=|s|): M = c*[[1,-t],[t,1]], t=s/c   -> ratio t, scale c
//   form1 (|s|> |c|): M = s*[[u,-1],[1,u]], u=c/s   -> ratio u, scale s
// ---------------------------------------------------------------------------
__global__ void sincos_kernel(const float* __restrict__ theta) {
    __shared__ float sc[NL * NQ];
    int i = threadIdx.x;
    if (i < NL * NQ) {
        float t = 0.5f * theta[i];
        float c = cosf(t), s = sinf(t);
        bool form = fabsf(s) > fabsf(c);
        float r     = form ? (c / s) : (s / c);
        float scale = form ? s : c;
        g_rf[i] = make_float2(r, form ? 1.0f : 0.0f);
        sc[i] = scale;
    }
    __syncthreads();
    if (i == 0) {
        float p = 1.0f;
        for (int k = 0; k < NL * NQ; k++) p *= sc[k];
        g_absC = fabsf(p);
    }
}

// ---------------------------------------------------------------------------
// Fast-Givens butterflies (1 FFMA per element per stage).
//   form0: a' = a - r*b ; b' = b + r*a
//   form1: a' = r*a - b ; b' = r*b + a
// ---------------------------------------------------------------------------
__device__ __forceinline__ float xsign(float v, uint32_t sg) {
    return __uint_as_float(__float_as_uint(v) ^ sg);
}

__device__ __forceinline__ void stage_reg_fg(float e[32], int m, float2 rf) {
    float r = rf.x;
    if (rf.y == 0.0f) {
#pragma unroll
        for (int j = 0; j < 32; j++)
            if ((j & m) == 0) {
                float a = e[j], b = e[j | m];
                e[j]     = fmaf(-r, b, a);
                e[j | m] = fmaf( r, a, b);
            }
    } else {
#pragma unroll
        for (int j = 0; j < 32; j++)
            if ((j & m) == 0) {
                float a = e[j], b = e[j | m];
                e[j]     = fmaf(r, a, -b);
                e[j | m] = fmaf(r, b,  a);
            }
    }
}

__device__ __forceinline__ void stage_xlane_fg(float e[32], int kbit, float2 rf, int lane) {
    int bit = (lane >> kbit) & 1;
    if (rf.y == 0.0f) {
        float rs = bit ? rf.x : -rf.x;         // a' = a - r*o ; b' = b + r*o
#pragma unroll
        for (int j = 0; j < 32; j++) {
            float o = __shfl_xor_sync(0xffffffffu, e[j], 1 << kbit);
            e[j] = fmaf(rs, o, e[j]);
        }
    } else {
        float r = rf.x;                        // a' = r*a - o ; b' = r*b + o
        uint32_t sg = bit ? 0u : 0x80000000u;  // sign applied to o via ALU XOR
#pragma unroll
        for (int j = 0; j < 32; j++) {
            float o = __shfl_xor_sync(0xffffffffu, e[j], 1 << kbit);
            e[j] = fmaf(r, e[j], xsign(o, sg));
        }
    }
}

// gray decode (p such that p ^ (p>>1) = g)
__device__ __host__ __forceinline__ constexpr int gdec(int g) {
    int p = g;
    p ^= p >> 1; p ^= p >> 2; p ^= p >> 4; p ^= p >> 8; p ^= p >> 16;
    return p;
}

// ---------------------------------------------------------------------------
// HIGH kernel: qubits 0..4 (index bits 19:15). Pure register butterflies,
// coalesced, in-place capable. k bit b <-> qubit 4-b.
// ---------------------------------------------------------------------------
__global__ void __launch_bounds__(512, 3) high_kernel(const float* __restrict__ in,
                                                      float* __restrict__ out,
                                                      int layer) {
    const int blk = blockIdx.x;   // 1024 = 16 batches * 64 windows of 512
    const size_t off = ((size_t)(blk >> 6) << 20) + (size_t)(blk & 63) * 512 + threadIdx.x;

    float e[32];
    const float* p = in + off;
#pragma unroll
    for (int k = 0; k < 32; k++) e[k] = p[(size_t)k << 15];

    const float2* rf = g_rf + layer * NQ;
    stage_reg_fg(e, 1,  rf[4]);
    stage_reg_fg(e, 2,  rf[3]);
    stage_reg_fg(e, 4,  rf[2]);
    stage_reg_fg(e, 8,  rf[1]);
    stage_reg_fg(e, 16, rf[0]);

    float* q = out + off;
#pragma unroll
    for (int k = 0; k < 32; k++) q[(size_t)k << 15] = e[k];
}

// ---------------------------------------------------------------------------
// LOW kernel: qubits 5..19 inside contiguous 32768-float tiles.
// 1024 threads, 32 regs/thread. m bit b <-> qubit 19-b.
// Phase1 (m = j*1024 + w*32 + t): shuffles bits 4:0 (q19..15), regs bits 14:10 (q9..5)
// smem transpose (reg bits <-> warp bits), Phase2: regs bits 9:5 (q14..10).
// Store folds CNOT-chain perm (gray-decode scatter); FINAL also applies |C|*|.|.
// ---------------------------------------------------------------------------
template <bool FINAL>
__global__ void __launch_bounds__(1024, 1) low_kernel(const float* __restrict__ in,
                                                      float* __restrict__ out,
                                                      int layer) {
    extern __shared__ float sm[];          // 32768 floats = 128 KB
    const int t = threadIdx.x & 31;
    const int w = threadIdx.x >> 5;
    const size_t tbase = (size_t)blockIdx.x << 15;   // grid = 512 tiles

    float e[32];
    const float* p = in + tbase;
#pragma unroll
    for (int j = 0; j < 32; j++) e[j] = p[j * 1024 + w * 32 + t];

    const float2* rf = g_rf + layer * NQ;
    stage_xlane_fg(e, 0, rf[19], t);
    stage_xlane_fg(e, 1, rf[18], t);
    stage_xlane_fg(e, 2, rf[17], t);
    stage_xlane_fg(e, 3, rf[16], t);
    stage_xlane_fg(e, 4, rf[15], t);
    stage_reg_fg(e, 1,  rf[9]);
    stage_reg_fg(e, 2,  rf[8]);
    stage_reg_fg(e, 4,  rf[7]);
    stage_reg_fg(e, 8,  rf[6]);
    stage_reg_fg(e, 16, rf[5]);

#pragma unroll
    for (int j = 0; j < 32; j++) sm[j * 1024 + w * 32 + t] = e[j];
    __syncthreads();
#pragma unroll
    for (int j = 0; j < 32; j++) e[j] = sm[w * 1024 + j * 32 + t];

    stage_reg_fg(e, 1,  rf[14]);
    stage_reg_fg(e, 2,  rf[13]);
    stage_reg_fg(e, 4,  rf[12]);
    stage_reg_fg(e, 8,  rf[11]);
    stage_reg_fg(e, 16, rf[10]);

    const int    tile20 = (int)(tbase & (DIM - 1));
    const size_t bbase  = tbase & ~((size_t)(DIM - 1));
    const int    pbase  = gdec(tile20 + (w << 10) + t);
    if (FINAL) {
        const float absC = g_absC;
#pragma unroll
        for (int j = 0; j < 32; j++) {
            int pp = pbase ^ gdec(j << 5);
            out[bbase + pp] = fabsf(e[j]) * absC;
        }
    } else {
#pragma unroll
        for (int j = 0; j < 32; j++) {
            int pp = pbase ^ gdec(j << 5);
            out[bbase + pp] = e[j];
        }
    }
}

// ---------------------------------------------------------------------------
extern "C" void kernel_launch(void* const* d_in, const int* in_sizes, int n_in,
                              void* d_out, int out_size) {
    const float* x     = (const float*)d_in[0];
    const float* theta = (const float*)d_in[1];
    float*       out   = (float*)d_out;

    float *bA = nullptr, *bB = nullptr;
    cudaGetSymbolAddress((void**)&bA, g_bufA);
    cudaGetSymbolAddress((void**)&bB, g_bufB);

    const int SMEM = 32768 * sizeof(float);
    cudaFuncSetAttribute(low_kernel<false>, cudaFuncAttributeMaxDynamicSharedMemorySize, SMEM);
    cudaFuncSetAttribute(low_kernel<true>,  cudaFuncAttributeMaxDynamicSharedMemorySize, SMEM);

    sincos_kernel<<<1, 128>>>(theta);

    high_kernel<<<1024, 512>>>(x,  bA, 0);
    low_kernel<false><<<512, 1024, SMEM>>>(bA, bB, 0);
    high_kernel<<<1024, 512>>>(bB, bB, 1);
    low_kernel<false><<<512, 1024, SMEM>>>(bB, bA, 1);
    high_kernel<<<1024, 512>>>(bA, bA, 2);
    low_kernel<false><<<512, 1024, SMEM>>>(bA, bB, 2);
    high_kernel<<<1024, 512>>>(bB, bB, 3);
    low_kernel<true><<<512, 1024, SMEM>>>(bB, out, 3);
}

// round 4
// speedup vs baseline: 1.3759x; 1.0332x over previous
#include <cuda_runtime.h>
#include <math.h>
#include <stdint.h>

#define NQ    20
#define NL    4
#define BATCH 16
#define DIM   (1 << NQ)
#define TOTAL (BATCH * DIM)

#define CB      8                      // batches per chunk (hot set = 2*CB*4MB = 64MB < L2)
#define NCHUNK  (BATCH / CB)

// Per-chunk scratch ping-pong buffers (reused across chunks -> L2 stays hot)
__device__ float  g_bufA[CB * DIM];
__device__ float  g_bufB[CB * DIM];
__device__ float2 g_rf[NL * NQ];   // .x = ratio (|r|<=1), .y = form (0 or 1)
__device__ float  g_absC;          // |product of per-gate scales|

// ---------------------------------------------------------------------------
// Fast-Givens precompute.
//   form0 (|c|>=|s|): M = c*[[1,-t],[t,1]], t=s/c
//   form1 (|s|> |c|): M = s*[[u,-1],[1,u]], u=c/s
// ---------------------------------------------------------------------------
__global__ void sincos_kernel(const float* __restrict__ theta) {
    __shared__ float sc[NL * NQ];
    int i = threadIdx.x;
    if (i < NL * NQ) {
        float t = 0.5f * theta[i];
        float c = cosf(t), s = sinf(t);
        bool form = fabsf(s) > fabsf(c);
        g_rf[i] = make_float2(form ? (c / s) : (s / c), form ? 1.0f : 0.0f);
        sc[i] = form ? s : c;
    }
    __syncthreads();
    if (i == 0) {
        float p = 1.0f;
        for (int k = 0; k < NL * NQ; k++) p *= sc[k];
        g_absC = fabsf(p);
    }
}

// ---------------------------------------------------------------------------
// Fast-Givens butterflies (1 FFMA per element per stage).
// ---------------------------------------------------------------------------
__device__ __forceinline__ float xsign(float v, uint32_t sg) {
    return __uint_as_float(__float_as_uint(v) ^ sg);
}

__device__ __forceinline__ void stage_reg_fg(float e[32], int m, float2 rf) {
    float r = rf.x;
    if (rf.y == 0.0f) {
#pragma unroll
        for (int j = 0; j < 32; j++)
            if ((j & m) == 0) {
                float a = e[j], b = e[j | m];
                e[j]     = fmaf(-r, b, a);
                e[j | m] = fmaf( r, a, b);
            }
    } else {
#pragma unroll
        for (int j = 0; j < 32; j++)
            if ((j & m) == 0) {
                float a = e[j], b = e[j | m];
                e[j]     = fmaf(r, a, -b);
                e[j | m] = fmaf(r, b,  a);
            }
    }
}

__device__ __forceinline__ void stage_xlane_fg(float e[32], int kbit, float2 rf, int lane) {
    int bit = (lane >> kbit) & 1;
    if (rf.y == 0.0f) {
        float rs = bit ? rf.x : -rf.x;
#pragma unroll
        for (int j = 0; j < 32; j++) {
            float o = __shfl_xor_sync(0xffffffffu, e[j], 1 << kbit);
            e[j] = fmaf(rs, o, e[j]);
        }
    } else {
        float r = rf.x;
        uint32_t sg = bit ? 0u : 0x80000000u;
#pragma unroll
        for (int j = 0; j < 32; j++) {
            float o = __shfl_xor_sync(0xffffffffu, e[j], 1 << kbit);
            e[j] = fmaf(r, e[j], xsign(o, sg));
        }
    }
}

// gray decode (p such that p ^ (p>>1) = g)
__device__ __host__ __forceinline__ constexpr int gdec(int g) {
    int p = g;
    p ^= p >> 1; p ^= p >> 2; p ^= p >> 4; p ^= p >> 8; p ^= p >> 16;
    return p;
}

// ---------------------------------------------------------------------------
// HIGH kernel: qubits 0..4 (index bits 19:15). Register butterflies,
// coalesced, in-place capable. Pointers are pre-offset to the chunk.
// ---------------------------------------------------------------------------
__global__ void __launch_bounds__(512, 3) high_kernel(const float* __restrict__ in,
                                                      float* __restrict__ out,
                                                      int layer) {
    const int blk = blockIdx.x;   // CB*64 blocks: batch = blk>>6, window = blk&63
    const size_t off = ((size_t)(blk >> 6) << 20) + (size_t)(blk & 63) * 512 + threadIdx.x;

    float e[32];
    const float* p = in + off;
#pragma unroll
    for (int k = 0; k < 32; k++) e[k] = p[(size_t)k << 15];

    const float2* rf = g_rf + layer * NQ;
    stage_reg_fg(e, 1,  rf[4]);
    stage_reg_fg(e, 2,  rf[3]);
    stage_reg_fg(e, 4,  rf[2]);
    stage_reg_fg(e, 8,  rf[1]);
    stage_reg_fg(e, 16, rf[0]);

    float* q = out + off;
#pragma unroll
    for (int k = 0; k < 32; k++) q[(size_t)k << 15] = e[k];
}

// ---------------------------------------------------------------------------
// LOW kernel: qubits 5..19 inside contiguous 32768-float tiles.
// 1024 threads, 32 regs/thread. Phase1: 5 shuffle + 5 reg stages; smem
// transpose; Phase2: 5 reg stages. Store folds the CNOT-chain permutation
// (gray-decode scatter, one 128B line per warp); FINAL applies |C|*|.|.
// ---------------------------------------------------------------------------
template <bool FINAL>
__global__ void __launch_bounds__(1024, 1) low_kernel(const float* __restrict__ in,
                                                      float* __restrict__ out,
                                                      int layer) {
    extern __shared__ float sm[];          // 32768 floats = 128 KB
    const int t = threadIdx.x & 31;
    const int w = threadIdx.x >> 5;
    const size_t tbase = (size_t)blockIdx.x << 15;   // grid = CB*32 tiles

    float e[32];
    const float* p = in + tbase;
#pragma unroll
    for (int j = 0; j < 32; j++) e[j] = p[j * 1024 + w * 32 + t];

    const float2* rf = g_rf + layer * NQ;
    stage_xlane_fg(e, 0, rf[19], t);
    stage_xlane_fg(e, 1, rf[18], t);
    stage_xlane_fg(e, 2, rf[17], t);
    stage_xlane_fg(e, 3, rf[16], t);
    stage_xlane_fg(e, 4, rf[15], t);
    stage_reg_fg(e, 1,  rf[9]);
    stage_reg_fg(e, 2,  rf[8]);
    stage_reg_fg(e, 4,  rf[7]);
    stage_reg_fg(e, 8,  rf[6]);
    stage_reg_fg(e, 16, rf[5]);

#pragma unroll
    for (int j = 0; j < 32; j++) sm[j * 1024 + w * 32 + t] = e[j];
    __syncthreads();
#pragma unroll
    for (int j = 0; j < 32; j++) e[j] = sm[w * 1024 + j * 32 + t];

    stage_reg_fg(e, 1,  rf[14]);
    stage_reg_fg(e, 2,  rf[13]);
    stage_reg_fg(e, 4,  rf[12]);
    stage_reg_fg(e, 8,  rf[11]);
    stage_reg_fg(e, 16, rf[10]);

    const int    tile20 = (int)(tbase & (DIM - 1));
    const size_t bbase  = tbase & ~((size_t)(DIM - 1));
    const int    pbase  = gdec(tile20 + (w << 10) + t);
    if (FINAL) {
        const float absC = g_absC;
#pragma unroll
        for (int j = 0; j < 32; j++) {
            int pp = pbase ^ gdec(j << 5);
            out[bbase + pp] = fabsf(e[j]) * absC;
        }
    } else {
#pragma unroll
        for (int j = 0; j < 32; j++) {
            int pp = pbase ^ gdec(j << 5);
            out[bbase + pp] = e[j];
        }
    }
}

// ---------------------------------------------------------------------------
extern "C" void kernel_launch(void* const* d_in, const int* in_sizes, int n_in,
                              void* d_out, int out_size) {
    const float* x     = (const float*)d_in[0];
    const float* theta = (const float*)d_in[1];
    float*       out   = (float*)d_out;

    float *bA = nullptr, *bB = nullptr;
    cudaGetSymbolAddress((void**)&bA, g_bufA);
    cudaGetSymbolAddress((void**)&bB, g_bufB);

    const int SMEM = 32768 * sizeof(float);
    cudaFuncSetAttribute(low_kernel<false>, cudaFuncAttributeMaxDynamicSharedMemorySize, SMEM);
    cudaFuncSetAttribute(low_kernel<true>,  cudaFuncAttributeMaxDynamicSharedMemorySize, SMEM);

    sincos_kernel<<<1, 128>>>(theta);

    const int GH = CB * 64;   // HIGH grid per chunk
    const int GL = CB * 32;   // LOW grid per chunk

    for (int c = 0; c < NCHUNK; c++) {
        const float* xc = x   + ((size_t)c * CB << 20);
        float*       oc = out + ((size_t)c * CB << 20);

        high_kernel<<<GH, 512>>>(xc, bA, 0);
        low_kernel<false><<<GL, 1024, SMEM>>>(bA, bB, 0);
        high_kernel<<<GH, 512>>>(bB, bB, 1);
        low_kernel<false><<<GL, 1024, SMEM>>>(bB, bA, 1);
        high_kernel<<<GH, 512>>>(bA, bA, 2);
        low_kernel<false><<<GL, 1024, SMEM>>>(bA, bB, 2);
        high_kernel<<<GH, 512>>>(bB, bB, 3);
        low_kernel<true><<<GL, 1024, SMEM>>>(bB, oc, 3);
    }
}